// round 12
// baseline (speedup 1.0000x reference)
#include <cuda_runtime.h>
#include <cuda_bf16.h>

// HMM forward DP (softmax semiring), strip-pipelined wavefront.
// theta: (2048, 2048, 3) f32, A: (3,3) f32, out: scalar f32.

#define NEG_INF   (-1.0e8f)
#define NDIM      2048
#define MCOLS     2048
#define HROWS     32
#define NBLK      (NDIM / HROWS)   /* 64 */

// handoff: bottom-row results of each strip, (m, e0, e1, e2) per column
__device__ float4 gHand[NBLK][MCOLS + 8];
__device__ int    gProg[NBLK];
__device__ float  gB[9];            // exp(A[s][k])

__global__ void hmm_init(const float* __restrict__ A) {
    int t = threadIdx.x;
    if (t < NBLK) gProg[t] = 0;
    if (t < 9)    gB[t] = __expf(A[t]);
}

__device__ __forceinline__ int ld_acq(const int* p) {
    int v;
    asm volatile("ld.acquire.gpu.global.b32 %0, [%1];" : "=r"(v) : "l"(p) : "memory");
    return v;
}
__device__ __forceinline__ void st_rel(int* p, int v) {
    asm volatile("st.release.gpu.global.b32 [%0], %1;" :: "l"(p), "r"(v) : "memory");
}

__global__ void __launch_bounds__(HROWS, 1)
hmm_wave(const float* __restrict__ theta, float* __restrict__ out) {
    const int p = blockIdx.x;
    const int l = threadIdx.x;

    // transition weights exp(A[s][k])
    const float B00 = gB[0], B01 = gB[1], B02 = gB[2];
    const float B10 = gB[3], B11 = gB[4], B12 = gB[5];
    const float B20 = gB[6], B21 = gB[7], B22 = gB[8];

    // own history h = value of cell (r, j-1); init = column-0 border
    float h_m = NEG_INF, h_e0 = 1.f, h_e1 = 1.f, h_e2 = 1.f;
    // delayed shfl (lane l-1's value from two steps ago) -> P0 = (i-1, j-1)
    float s_m = NEG_INF, s_e0 = 1.f, s_e1 = 1.f, s_e2 = 1.f;

    // lane0 parent-prev (P0): block0 sees cell (0,0) = (m=0, e=1,1,1); else col-0 border
    float pp_m = (p == 0) ? 0.f : NEG_INF;
    float pp_e0 = 1.f, pp_e1 = 1.f, pp_e2 = 1.f;

    // theta addressing: lane l at step t computes cell (r = HROWS*p + l + 1, j = t - l),
    // using theta[r-1, j-1, :]  ->  offset = rowbase + t*3 - (l+1)*3
    const int rowbase = (HROWS * p + l) * (MCOLS * 3);
    const int lanesh  = (l + 1) * 3;

    // software-pipelined prefetch slots (distance 4)
    float4 pq[4];
    float th0[4], th1[4], th2[4];
    #pragma unroll
    for (int k = 0; k < 4; k++) {
        pq[k] = make_float4(NEG_INF, 1.f, 1.f, 1.f);   // block0: row-0 border, constant
        th0[k] = th1[k] = th2[k] = 0.f;
    }

    int avail = 0;
    const float4* parentRow = gHand[(p > 0) ? (p - 1) : 0];

    // ---- prologue: prefetch steps 1..4 ----
    if (l == 0 && p > 0) {
        int need = 4;
        while (avail < need) avail = ld_acq(&gProg[p - 1]);
        #pragma unroll
        for (int k = 0; k < 4; k++) pq[k] = __ldcg(&parentRow[1 + k]);
    }
    #pragma unroll
    for (int k = 0; k < 4; k++) {
        int t = 1 + k;
        if (t > l) {
            int off = rowbase + t * 3 - lanesh;
            th0[k] = theta[off];
            th1[k] = theta[off + 1];
            th2[k] = theta[off + 2];
        }
    }

    const int TEND = MCOLS + HROWS - 1;   // 2079
    for (int tg = 1; tg <= TEND; tg += 4) {
        // group-level flag check for the next 4 prefetched parent columns
        if (l == 0 && p > 0) {
            int need = tg + 7;
            if (need > MCOLS) need = MCOLS;
            if (avail < need) {
                do { avail = ld_acq(&gProg[p - 1]); } while (avail < need);
            }
        }
        #pragma unroll
        for (int k = 0; k < 4; k++) {
            const int t = tg + k;
            // consume prefetched values
            const float t0 = th0[k], t1 = th1[k], t2 = th2[k];
            const float4 P1q = pq[k];
            // issue prefetch for step t+4 (latency hidden behind 4 chain steps)
            {
                const int tp = t + 4;
                if (l == 0 && p > 0 && tp <= MCOLS) pq[k] = __ldcg(&parentRow[tp]);
                if (tp > l && tp <= MCOLS + l) {
                    int off = rowbase + tp * 3 - lanesh;
                    th0[k] = theta[off];
                    th1[k] = theta[off + 1];
                    th2[k] = theta[off + 2];
                }
            }
            // lane l-1's step-(t-1) value -> P1 = (i-1, j)
            const float q_m  = __shfl_up_sync(0xffffffffu, h_m, 1);
            const float q_e0 = __shfl_up_sync(0xffffffffu, h_e0, 1);
            const float q_e1 = __shfl_up_sync(0xffffffffu, h_e1, 1);
            const float q_e2 = __shfl_up_sync(0xffffffffu, h_e2, 1);

            float P1m = q_m, P1e0 = q_e0, P1e1 = q_e1, P1e2 = q_e2;
            float P0m = s_m, P0e0 = s_e0, P0e1 = s_e1, P0e2 = s_e2;
            if (l == 0) {   // parent strip supplies (i-1, j) and (i-1, j-1)
                P1m = P1q.x; P1e0 = P1q.y; P1e1 = P1q.z; P1e2 = P1q.w;
                P0m = pp_m;  P0e0 = pp_e0; P0e1 = pp_e1; P0e2 = pp_e2;
            }

            // dots: sum_k e_pred[k] * exp(A[s][k])
            const float d0 = fmaf(P0e2, B02, fmaf(P0e1, B01, P0e0 * B00));
            const float d1 = fmaf(P1e2, B12, fmaf(P1e1, B11, P1e0 * B10));
            const float d2 = fmaf(h_e2, B22, fmaf(h_e1, B21, h_e0 * B20));

            const float V0 = t0 + P0m + __logf(d0);
            const float V1 = t1 + P1m + __logf(d1);
            const float V2 = t2 + h_m + __logf(d2);

            const float vm  = fmaxf(V0, fmaxf(V1, V2));
            const float ne0 = __expf(V0 - vm);
            const float ne1 = __expf(V1 - vm);
            const float ne2 = __expf(V2 - vm);

            const bool active = (t > l) && (t <= MCOLS + l);

            // delayed-shfl capture (unconditional, pure register bookkeeping)
            s_m = q_m; s_e0 = q_e0; s_e1 = q_e1; s_e2 = q_e2;

            if (active) {
                h_m = vm; h_e0 = ne0; h_e1 = ne1; h_e2 = ne2;
                if (l == 0) { pp_m = P1m; pp_e0 = P1e0; pp_e1 = P1e1; pp_e2 = P1e2; }
                if (l == HROWS - 1) {
                    gHand[p][t - (HROWS - 1)] = make_float4(vm, ne0, ne1, ne2);
                }
            }
        }
        // publish progress every other group (granularity = 8 columns)
        if (l == HROWS - 1 && ((tg & 4) == 0)) {
            int jd = tg + 3 - (HROWS - 1);
            if (jd >= 1) st_rel(&gProg[p], jd);
        }
    }
    if (l == HROWS - 1) st_rel(&gProg[p], MCOLS);

    // final: Vt = lse_k V[N, M, k] = m + log(e0+e1+e2), held by last strip's bottom lane
    if (p == NBLK - 1 && l == HROWS - 1)
        out[0] = h_m + __logf(h_e0 + h_e1 + h_e2);
}

extern "C" void kernel_launch(void* const* d_in, const int* in_sizes, int n_in,
                              void* d_out, int out_size) {
    const float* theta = (const float*)d_in[0];
    const float* A     = (const float*)d_in[1];
    float* out = (float*)d_out;
    (void)in_sizes; (void)n_in; (void)out_size;

    hmm_init<<<1, 64>>>(A);
    hmm_wave<<<NBLK, HROWS>>>(theta, out);
}